// round 6
// baseline (speedup 1.0000x reference)
#include <cuda_runtime.h>
#include <cuda_fp16.h>
#include <math_constants.h>

// Problem constants
#define B_   8
#define N_   8192
#define C_   512
#define NB_  256          // number of token-blocks (N/32)
#define TOK_STRIDE 16384  // 32 * C_  (elem stride between consecutive block j at fixed s)
#define TOT 33554432      // B_*N_*C_

// Single scratch global: K and V in fp16 (64 MB + 64 MB = 128 MB total).
// q (fp32) lives in d_out and is overwritten in-place by the attention output.
__device__ __half g_kv[2u * TOT];

// ---------------------------------------------------------------------------
// Kernel 1: QKV GEMM [65536,512] x [512,1536] + bias.
// Epilogue de-splits head-interleaved layout: col n -> (hh=n/192, part=(n%192)/64,
// d=n%64), channel c = hh*64+d.  part0 -> q fp32 in d_out; part1/2 -> fp16 g_kv.
// Double-buffered 128x128x16.
// ---------------------------------------------------------------------------
__global__ void __launch_bounds__(256) qkv_gemm(const float* __restrict__ X,
                                                const float* __restrict__ W,
                                                const float* __restrict__ bias,
                                                float* __restrict__ Qf)
{
    __shared__ float As[2][16][132];
    __shared__ float Bs[2][16][128];

    const int tid = threadIdx.x;
    const int tx = tid & 15, ty = tid >> 4;
    const int m0 = blockIdx.y * 128;
    const int n0 = blockIdx.x * 128;

    const int ar = tid >> 2;          // 0..63
    const int ac = (tid & 3) << 2;    // 0,4,8,12
    const int br = tid >> 5;          // 0..7
    const int bc = (tid & 31) << 2;   // 0..124

    const float* Ap0 = X + (size_t)(m0 + ar) * 512 + ac;
    const float* Ap1 = X + (size_t)(m0 + ar + 64) * 512 + ac;
    const float* Bp0 = W + (size_t)br * 1536 + n0 + bc;
    const float* Bp1 = W + (size_t)(br + 8) * 1536 + n0 + bc;

    float acc[8][8];
#pragma unroll
    for (int i = 0; i < 8; i++)
#pragma unroll
        for (int j = 0; j < 8; j++) acc[i][j] = 0.f;

    {   // prologue: tile 0
        float4 a0 = *(const float4*)(Ap0);
        float4 a1 = *(const float4*)(Ap1);
        float4 b0 = *(const float4*)(Bp0);
        float4 b1 = *(const float4*)(Bp1);
        As[0][ac + 0][ar] = a0.x; As[0][ac + 1][ar] = a0.y;
        As[0][ac + 2][ar] = a0.z; As[0][ac + 3][ar] = a0.w;
        As[0][ac + 0][ar + 64] = a1.x; As[0][ac + 1][ar + 64] = a1.y;
        As[0][ac + 2][ar + 64] = a1.z; As[0][ac + 3][ar + 64] = a1.w;
        *(float4*)(&Bs[0][br][bc])     = b0;
        *(float4*)(&Bs[0][br + 8][bc]) = b1;
    }
    __syncthreads();

    int buf = 0;
    for (int kt = 0; kt < 512; kt += 16) {
        const bool more = (kt + 16) < 512;
        float4 na0, na1, nb0, nb1;
        if (more) {
            na0 = *(const float4*)(Ap0 + kt + 16);
            na1 = *(const float4*)(Ap1 + kt + 16);
            nb0 = *(const float4*)(Bp0 + (size_t)(kt + 16) * 1536);
            nb1 = *(const float4*)(Bp1 + (size_t)(kt + 16) * 1536);
        }
#pragma unroll
        for (int k = 0; k < 16; k++) {
            float a[8], b[8];
            *(float4*)(a)     = *(const float4*)&As[buf][k][ty * 4];
            *(float4*)(a + 4) = *(const float4*)&As[buf][k][ty * 4 + 64];
            *(float4*)(b)     = *(const float4*)&Bs[buf][k][tx * 4];
            *(float4*)(b + 4) = *(const float4*)&Bs[buf][k][tx * 4 + 64];
#pragma unroll
            for (int i = 0; i < 8; i++)
#pragma unroll
                for (int j = 0; j < 8; j++) acc[i][j] += a[i] * b[j];
        }
        if (more) {
            int nx = buf ^ 1;
            As[nx][ac + 0][ar] = na0.x; As[nx][ac + 1][ar] = na0.y;
            As[nx][ac + 2][ar] = na0.z; As[nx][ac + 3][ar] = na0.w;
            As[nx][ac + 0][ar + 64] = na1.x; As[nx][ac + 1][ar + 64] = na1.y;
            As[nx][ac + 2][ar + 64] = na1.z; As[nx][ac + 3][ar + 64] = na1.w;
            *(float4*)(&Bs[nx][br][bc])     = nb0;
            *(float4*)(&Bs[nx][br + 8][bc]) = nb1;
        }
        __syncthreads();
        buf ^= 1;
    }

    // Epilogue: bias + scatter (each float4 stays within one part / one head)
#pragma unroll
    for (int i = 0; i < 8; i++) {
        int m = m0 + ty * 4 + (i & 3) + ((i >> 2) << 6);
#pragma unroll
        for (int jj = 0; jj < 2; jj++) {
            int n = n0 + tx * 4 + (jj << 6);
            float4 v;
            v.x = acc[i][jj * 4 + 0] + bias[n + 0];
            v.y = acc[i][jj * 4 + 1] + bias[n + 1];
            v.z = acc[i][jj * 4 + 2] + bias[n + 2];
            v.w = acc[i][jj * 4 + 3] + bias[n + 3];
            int part = (n % 192) >> 6;
            int c = ((n / 192) << 6) + (n & 63);
            size_t idx = (size_t)m * 512 + c;
            if (part == 0) {
                *(float4*)&Qf[idx] = v;
            } else {
                __half2 h0 = __floats2half2_rn(v.x, v.y);
                __half2 h1 = __floats2half2_rn(v.z, v.w);
                uint2 pk;
                pk.x = *(unsigned int*)&h0;
                pk.y = *(unsigned int*)&h1;
                *(uint2*)&g_kv[(part == 1 ? 0u : (unsigned)TOT) + idx] = pk;
            }
        }
    }
}

// ---------------------------------------------------------------------------
// Kernel 2: banded block attention.
// CTA = (b, s, i-tile of 64 blocks). j-window = 192 at jlo.
// Q fp32 from IO (=d_out); K,V fp16 from g_kv; att written back into IO
// (safe: q rows read only by owning CTA, fully consumed before phase 2).
// ---------------------------------------------------------------------------
#define ATTN_SMEM_FLOATS (12800 + 12288)   // S[64][200] + max(Qs+Ks, Vs[192][64])
#define ATTN_SMEM_BYTES  (ATTN_SMEM_FLOATS * 4)

__global__ void __launch_bounds__(256) attn_kernel(float* __restrict__ IO)
{
    extern __shared__ float sm[];
    float* S  = sm;                 // [64][200]
    float* U  = sm + 12800;
    float* Qs = U;                  // [32][65]  (k-major, transposed)
    float* Ks = U + 32 * 65;        // [32][193]
    float* Vs = U;                  // [192][64] (phase 2, aliases Qs/Ks)

    const int tid = threadIdx.x;
    const int tx = tid & 15, ty = tid >> 4;
    const int i0 = blockIdx.x * 64;
    const int s  = blockIdx.y;
    const int b  = blockIdx.z;
    const int jlo = (i0 - 64 > 0) ? (i0 - 64) : 0;

    const size_t base = ((size_t)b * N_ + s) * C_;
    const float* Qg = IO + base;
    const __half* Kg = g_kv + base;
    const __half* Vg = g_kv + TOT + base;
    float* Ob = IO + base;

    float acc[4][12];
#pragma unroll
    for (int r = 0; r < 4; r++)
#pragma unroll
        for (int c = 0; c < 12; c++) acc[r][c] = 0.f;

    // ---- Phase 1: scores = Q K^T over K=512 in chunks of 32 ----
    for (int kc = 0; kc < 512; kc += 32) {
#pragma unroll
        for (int it = 0; it < 8; it++) {
            int idx = it * 256 + tid;
            int r = idx >> 5, c = idx & 31;
            Qs[c * 65 + r] = Qg[(size_t)(i0 + r) * TOK_STRIDE + kc + c];
        }
        // K tile: 192 j x 32 c, half2 vector loads (12 iters)
#pragma unroll
        for (int it = 0; it < 12; it++) {
            int idx = it * 256 + tid;
            int j = idx >> 4, c = (idx & 15) << 1;
            int jg = jlo + j;
            float f0 = 0.f, f1 = 0.f;
            if (jg < NB_) {
                __half2 h = *(const __half2*)
                    &Kg[(size_t)jg * TOK_STRIDE + kc + c];
                float2 f = __half22float2(h);
                f0 = f.x; f1 = f.y;
            }
            Ks[c * 193 + j]       = f0;
            Ks[(c + 1) * 193 + j] = f1;
        }
        __syncthreads();
#pragma unroll 8
        for (int k = 0; k < 32; k++) {
            float a[4], bb[12];
#pragma unroll
            for (int r = 0; r < 4; r++) a[r] = Qs[k * 65 + ty + 16 * r];
#pragma unroll
            for (int c = 0; c < 12; c++) bb[c] = Ks[k * 193 + tx + 16 * c];
#pragma unroll
            for (int r = 0; r < 4; r++)
#pragma unroll
                for (int c = 0; c < 12; c++) acc[r][c] += a[r] * bb[c];
        }
        __syncthreads();
    }

    // ---- masked scores -> smem ----
#pragma unroll
    for (int r = 0; r < 4; r++) {
        int row = ty + 16 * r;
        int gi = i0 + row;
#pragma unroll
        for (int c = 0; c < 12; c++) {
            int col = tx + 16 * c;
            int jg = jlo + col;
            bool valid = (jg < NB_) && (jg >= gi - 64) && (jg <= gi + 64);
            S[row * 200 + col] = valid ? acc[r][c] * 0.125f : -CUDART_INF_F;
        }
    }
    __syncthreads();

    // ---- softmax over the 192-wide window ----
    {
        int warp = tid >> 5, lane = tid & 31;
        for (int row = warp; row < 64; row += 8) {
            float v[6];
            float m = -CUDART_INF_F;
#pragma unroll
            for (int t = 0; t < 6; t++) {
                v[t] = S[row * 200 + lane + 32 * t];
                m = fmaxf(m, v[t]);
            }
#pragma unroll
            for (int o = 16; o > 0; o >>= 1)
                m = fmaxf(m, __shfl_xor_sync(0xffffffffu, m, o));
            float sum = 0.f;
#pragma unroll
            for (int t = 0; t < 6; t++) { v[t] = expf(v[t] - m); sum += v[t]; }
#pragma unroll
            for (int o = 16; o > 0; o >>= 1)
                sum += __shfl_xor_sync(0xffffffffu, sum, o);
            float inv = 1.0f / sum;
#pragma unroll
            for (int t = 0; t < 6; t++) S[row * 200 + lane + 32 * t] = v[t] * inv;
        }
    }
    __syncthreads();

    // ---- Phase 2: out = P V, streamed over 64-wide C chunks ----
    for (int c0 = 0; c0 < 512; c0 += 64) {
        // V tile: 192 j x 64 c, half2 loads (24 iters)
#pragma unroll
        for (int it = 0; it < 24; it++) {
            int idx = it * 256 + tid;
            int j = idx >> 5, c = (idx & 31) << 1;
            int jg = jlo + j;
            float f0 = 0.f, f1 = 0.f;
            if (jg < NB_) {
                __half2 h = *(const __half2*)
                    &Vg[(size_t)jg * TOK_STRIDE + c0 + c];
                float2 f = __half22float2(h);
                f0 = f.x; f1 = f.y;
            }
            Vs[j * 64 + c]     = f0;
            Vs[j * 64 + c + 1] = f1;
        }
        __syncthreads();
        float o[4][4];
#pragma unroll
        for (int r = 0; r < 4; r++)
#pragma unroll
            for (int c = 0; c < 4; c++) o[r][c] = 0.f;
#pragma unroll 4
        for (int j = 0; j < 192; j++) {
            float4 vv = *(const float4*)&Vs[j * 64 + tx * 4];
#pragma unroll
            for (int r = 0; r < 4; r++) {
                float p = S[(ty * 4 + r) * 200 + j];
                o[r][0] += p * vv.x; o[r][1] += p * vv.y;
                o[r][2] += p * vv.z; o[r][3] += p * vv.w;
            }
        }
#pragma unroll
        for (int r = 0; r < 4; r++) {
            int row = ty * 4 + r;
            *(float4*)&Ob[(size_t)(i0 + row) * TOK_STRIDE + c0 + tx * 4] =
                make_float4(o[r][0], o[r][1], o[r][2], o[r][3]);
        }
        __syncthreads();
    }
}

// ---------------------------------------------------------------------------
// Kernel 3: in-place output projection on IO (=d_out).
// CTA owns 64 exclusive rows x full N=512: all reads of those rows complete
// (K loop) before the epilogue writes them. 512 threads, 8x8 per thread.
// ---------------------------------------------------------------------------
#define PROJ_SMEM_FLOATS (2 * 16 * 64 + 2 * 16 * 512)
#define PROJ_SMEM_BYTES  (PROJ_SMEM_FLOATS * 4)

__global__ void __launch_bounds__(512) proj_inplace(const float* __restrict__ W,
                                                    const float* __restrict__ bias,
                                                    float* __restrict__ IO)
{
    extern __shared__ float sm[];
    // As[buf][k][m] : sm[buf*1024 + k*64 + m]        (2*16*64)
    // Bs[buf][k][n] : sm[2048 + buf*8192 + k*512 + n] (2*16*512)
    float* Asm = sm;
    float* Bsm = sm + 2048;

    const int tid = threadIdx.x;
    const int tx = tid & 63;          // col group: cols tx + 64*c
    const int ty = tid >> 6;          // row group: rows ty*8 + i
    const int m0 = blockIdx.x * 64;

    const int arow = tid >> 3;        // 0..63
    const int akq  = (tid & 7) << 1;  // 0,2,..,14
    const int brow = tid >> 5;        // 0..15
    const int bcol = (tid & 31) << 2; // 0..124 (then +128*c)

    const float* Apt = IO + (size_t)(m0 + arow) * 512 + akq;
    const float* Bpt = W + (size_t)brow * 512 + bcol;

    float acc[8][8];
#pragma unroll
    for (int i = 0; i < 8; i++)
#pragma unroll
        for (int j = 0; j < 8; j++) acc[i][j] = 0.f;

    {   // prologue
        float2 a = *(const float2*)(Apt);
        Asm[akq * 64 + arow] = a.x;
        Asm[(akq + 1) * 64 + arow] = a.y;
#pragma unroll
        for (int c = 0; c < 4; c++)
            *(float4*)&Bsm[brow * 512 + bcol + 128 * c] =
                *(const float4*)(Bpt + 128 * c);
    }
    __syncthreads();

    int buf = 0;
    for (int kt = 0; kt < 512; kt += 16) {
        const bool more = (kt + 16) < 512;
        float2 na;
        float4 nb[4];
        if (more) {
            na = *(const float2*)(Apt + kt + 16);
#pragma unroll
            for (int c = 0; c < 4; c++)
                nb[c] = *(const float4*)(Bpt + (size_t)(kt + 16) * 512 + 128 * c);
        }
        const float* Ab = Asm + buf * 1024;
        const float* Bb = Bsm + buf * 8192;
#pragma unroll
        for (int k = 0; k < 16; k++) {
            float a[8], b[8];
#pragma unroll
            for (int i = 0; i < 8; i++) a[i] = Ab[k * 64 + ty * 8 + i];
#pragma unroll
            for (int c = 0; c < 8; c++) b[c] = Bb[k * 512 + tx + 64 * c];
#pragma unroll
            for (int i = 0; i < 8; i++)
#pragma unroll
                for (int c = 0; c < 8; c++) acc[i][c] += a[i] * b[c];
        }
        if (more) {
            int nx = buf ^ 1;
            Asm[nx * 1024 + akq * 64 + arow] = na.x;
            Asm[nx * 1024 + (akq + 1) * 64 + arow] = na.y;
#pragma unroll
            for (int c = 0; c < 4; c++)
                *(float4*)&Bsm[nx * 8192 + brow * 512 + bcol + 128 * c] = nb[c];
        }
        __syncthreads();
        buf ^= 1;
    }

    // Epilogue: write back the CTA's exclusive rows (all reads already done)
#pragma unroll
    for (int i = 0; i < 8; i++) {
        int row = m0 + ty * 8 + i;
#pragma unroll
        for (int c = 0; c < 8; c++) {
            int col = tx + 64 * c;
            IO[(size_t)row * 512 + col] = acc[i][c] + bias[col];
        }
    }
}

// ---------------------------------------------------------------------------
extern "C" void kernel_launch(void* const* d_in, const int* in_sizes, int n_in,
                              void* d_out, int out_size)
{
    const float* x     = (const float*)d_in[0];
    const float* Wqkv  = (const float*)d_in[1];
    const float* bqkv  = (const float*)d_in[2];
    const float* Wproj = (const float*)d_in[3];
    const float* bproj = (const float*)d_in[4];
    float* out = (float*)d_out;

    cudaFuncSetAttribute(attn_kernel, cudaFuncAttributeMaxDynamicSharedMemorySize,
                         ATTN_SMEM_BYTES);
    cudaFuncSetAttribute(proj_inplace, cudaFuncAttributeMaxDynamicSharedMemorySize,
                         PROJ_SMEM_BYTES);

    qkv_gemm<<<dim3(12, 512), 256>>>(x, Wqkv, bqkv, out);
    attn_kernel<<<dim3(4, 32, 8), 256, ATTN_SMEM_BYTES>>>(out);
    proj_inplace<<<1024, 512, PROJ_SMEM_BYTES>>>(Wproj, bproj, out);
}

// round 7
// speedup vs baseline: 1.4785x; 1.4785x over previous
#include <cuda_runtime.h>
#include <cuda_fp16.h>
#include <math_constants.h>
#include <cstdint>

// Problem constants
#define B_   8
#define N_   8192
#define C_   512
#define NB_  256          // number of token-blocks (N/32)
#define TOK_STRIDE 16384  // 32 * C_
#define TOT 33554432      // B_*N_*C_

// Single scratch global: K and V in fp16 (128 MB total). q fp32 lives in d_out.
__device__ __half g_kv[2u * TOT];

// ---------------------------------------------------------------------------
// helpers
// ---------------------------------------------------------------------------
__device__ __forceinline__ uint32_t sptr(const void* p) {
    return (uint32_t)__cvta_generic_to_shared(p);
}
__device__ __forceinline__ uint2 cvt2h2(float4 f) {
    __half2 h0 = __floats2half2_rn(f.x, f.y);
    __half2 h1 = __floats2half2_rn(f.z, f.w);
    uint2 r;
    r.x = *(uint32_t*)&h0;
    r.y = *(uint32_t*)&h1;
    return r;
}

#define LDM_X4(r0, r1, r2, r3, addr)                                         \
    asm volatile("ldmatrix.sync.aligned.m8n8.x4.shared.b16 {%0,%1,%2,%3}, [%4];" \
                 : "=r"(r0), "=r"(r1), "=r"(r2), "=r"(r3) : "r"(addr))
#define LDM_X4T(r0, r1, r2, r3, addr)                                        \
    asm volatile("ldmatrix.sync.aligned.m8n8.x4.trans.shared.b16 {%0,%1,%2,%3}, [%4];" \
                 : "=r"(r0), "=r"(r1), "=r"(r2), "=r"(r3) : "r"(addr))
#define MMA16816(c, a, b)                                                    \
    asm volatile("mma.sync.aligned.m16n8k16.row.col.f32.f16.f16.f32 "        \
                 "{%0,%1,%2,%3}, {%4,%5,%6,%7}, {%8,%9}, {%0,%1,%2,%3};"     \
                 : "+f"((c)[0]), "+f"((c)[1]), "+f"((c)[2]), "+f"((c)[3])    \
                 : "r"((a)[0]), "r"((a)[1]), "r"((a)[2]), "r"((a)[3]),       \
                   "r"((b)[0]), "r"((b)[1]))

// ---------------------------------------------------------------------------
// Kernel 1: QKV GEMM via fp16 tensor cores, fp32 accumulate.
// [65536,512] x [512,1536] + bias; on-the-fly fp32->fp16 in smem loaders.
// CTA 128x128x32, 8 warps (4x2), warp tile 32x64. Double-buffered.
// Epilogue de-splits head-interleave: part0 -> q fp32 in d_out; 1/2 -> fp16 g_kv.
// ---------------------------------------------------------------------------
__global__ void __launch_bounds__(256) qkv_mma(const float* __restrict__ X,
                                               const float* __restrict__ W,
                                               const float* __restrict__ bias,
                                               float* __restrict__ Qf)
{
    __shared__ __half As[2][128][40];   // [m][k], pitch 40 halves (80B: conflict-free ldmatrix)
    __shared__ __half Bs[2][32][136];   // [k][n], pitch 136 halves (272B)

    const int tid  = threadIdx.x;
    const int lane = tid & 31, wid = tid >> 5;
    const int wm = (wid & 3) << 5;      // warp row offset 0/32/64/96
    const int wn = (wid >> 2) << 6;     // warp col offset 0/64
    const int m0 = blockIdx.y << 7;
    const int n0 = blockIdx.x << 7;

    const int la_r = tid >> 1, la_k = (tid & 1) << 4;   // A: 1 row, 16 k
    const int lb_k = tid >> 3, lb_n = (tid & 7) << 4;   // B: 1 k, 16 n

    const float* Ap = X + (size_t)(m0 + la_r) * 512 + la_k;
    const float* Bp = W + (size_t)lb_k * 1536 + n0 + lb_n;

    float acc[2][8][4];
#pragma unroll
    for (int i = 0; i < 2; i++)
#pragma unroll
        for (int j = 0; j < 8; j++)
#pragma unroll
            for (int c = 0; c < 4; c++) acc[i][j][c] = 0.f;

    float4 fa[4], fb[4];
#pragma unroll
    for (int i = 0; i < 4; i++) fa[i] = *(const float4*)(Ap + 4 * i);
#pragma unroll
    for (int i = 0; i < 4; i++) fb[i] = *(const float4*)(Bp + 4 * i);

    // stage tile 0 into buffer 0
    {
        uint2 a0 = cvt2h2(fa[0]), a1 = cvt2h2(fa[1]), a2 = cvt2h2(fa[2]), a3 = cvt2h2(fa[3]);
        *(uint4*)&As[0][la_r][la_k]     = make_uint4(a0.x, a0.y, a1.x, a1.y);
        *(uint4*)&As[0][la_r][la_k + 8] = make_uint4(a2.x, a2.y, a3.x, a3.y);
        uint2 b0 = cvt2h2(fb[0]), b1 = cvt2h2(fb[1]), b2 = cvt2h2(fb[2]), b3 = cvt2h2(fb[3]);
        *(uint4*)&Bs[0][lb_k][lb_n]     = make_uint4(b0.x, b0.y, b1.x, b1.y);
        *(uint4*)&Bs[0][lb_k][lb_n + 8] = make_uint4(b2.x, b2.y, b3.x, b3.y);
    }
    __syncthreads();

    int buf = 0;
    for (int kt = 0; kt < 512; kt += 32) {
        const bool more = (kt + 32) < 512;
        if (more) {
#pragma unroll
            for (int i = 0; i < 4; i++) fa[i] = *(const float4*)(Ap + kt + 32 + 4 * i);
#pragma unroll
            for (int i = 0; i < 4; i++) fb[i] = *(const float4*)(Bp + (size_t)(kt + 32) * 1536 + 4 * i);
        }
#pragma unroll
        for (int kk = 0; kk < 2; kk++) {
            uint32_t af[2][4];
#pragma unroll
            for (int tm = 0; tm < 2; tm++) {
                uint32_t ad = sptr(&As[buf][wm + tm * 16 + (lane & 15)][kk * 16 + ((lane >> 4) << 3)]);
                LDM_X4(af[tm][0], af[tm][1], af[tm][2], af[tm][3], ad);
            }
            uint32_t bfr[8][2];
#pragma unroll
            for (int g16 = 0; g16 < 4; g16++) {
                uint32_t r0, r1, r2, r3;
                uint32_t bd = sptr(&Bs[buf][kk * 16 + (lane & 15)][wn + g16 * 16 + ((lane >> 4) << 3)]);
                LDM_X4T(r0, r1, r2, r3, bd);
                bfr[2 * g16][0] = r0;     bfr[2 * g16][1] = r1;
                bfr[2 * g16 + 1][0] = r2; bfr[2 * g16 + 1][1] = r3;
            }
#pragma unroll
            for (int tm = 0; tm < 2; tm++)
#pragma unroll
                for (int tn = 0; tn < 8; tn++)
                    MMA16816(acc[tm][tn], af[tm], bfr[tn]);
        }
        if (more) {
            int nx = buf ^ 1;
            uint2 a0 = cvt2h2(fa[0]), a1 = cvt2h2(fa[1]), a2 = cvt2h2(fa[2]), a3 = cvt2h2(fa[3]);
            *(uint4*)&As[nx][la_r][la_k]     = make_uint4(a0.x, a0.y, a1.x, a1.y);
            *(uint4*)&As[nx][la_r][la_k + 8] = make_uint4(a2.x, a2.y, a3.x, a3.y);
            uint2 b0 = cvt2h2(fb[0]), b1 = cvt2h2(fb[1]), b2 = cvt2h2(fb[2]), b3 = cvt2h2(fb[3]);
            *(uint4*)&Bs[nx][lb_k][lb_n]     = make_uint4(b0.x, b0.y, b1.x, b1.y);
            *(uint4*)&Bs[nx][lb_k][lb_n + 8] = make_uint4(b2.x, b2.y, b3.x, b3.y);
        }
        __syncthreads();
        buf ^= 1;
    }

    // Epilogue: fragment layout c0,c1=(row g, cols q*2,q*2+1), c2,c3=(row g+8).
    const int g = lane >> 2, q = lane & 3;
#pragma unroll
    for (int tm = 0; tm < 2; tm++) {
        int r0 = m0 + wm + tm * 16 + g;
#pragma unroll
        for (int tn = 0; tn < 8; tn++) {
            int col = n0 + wn + tn * 8 + (q << 1);
            float bx = bias[col], by = bias[col + 1];
            int part = (col % 192) >> 6;
            int c = ((col / 192) << 6) + (col & 63);
            float vx0 = acc[tm][tn][0] + bx, vy0 = acc[tm][tn][1] + by;
            float vx1 = acc[tm][tn][2] + bx, vy1 = acc[tm][tn][3] + by;
            if (part == 0) {
                *(float2*)&Qf[(size_t)r0 * 512 + c]       = make_float2(vx0, vy0);
                *(float2*)&Qf[(size_t)(r0 + 8) * 512 + c] = make_float2(vx1, vy1);
            } else {
                __half* dst = g_kv + (part == 1 ? 0u : (unsigned)TOT);
                *(__half2*)&dst[(size_t)r0 * 512 + c]       = __floats2half2_rn(vx0, vy0);
                *(__half2*)&dst[(size_t)(r0 + 8) * 512 + c] = __floats2half2_rn(vx1, vy1);
            }
        }
    }
}

// ---------------------------------------------------------------------------
// Kernel 2: banded block attention (unchanged from the passing Round-6 build).
// ---------------------------------------------------------------------------
#define ATTN_SMEM_FLOATS (12800 + 12288)
#define ATTN_SMEM_BYTES  (ATTN_SMEM_FLOATS * 4)

__global__ void __launch_bounds__(256) attn_kernel(float* __restrict__ IO)
{
    extern __shared__ float sm[];
    float* S  = sm;                 // [64][200]
    float* U  = sm + 12800;
    float* Qs = U;                  // [32][65]
    float* Ks = U + 32 * 65;        // [32][193]
    float* Vs = U;                  // [192][64] (phase 2 alias)

    const int tid = threadIdx.x;
    const int tx = tid & 15, ty = tid >> 4;
    const int i0 = blockIdx.x * 64;
    const int s  = blockIdx.y;
    const int b  = blockIdx.z;
    const int jlo = (i0 - 64 > 0) ? (i0 - 64) : 0;

    const size_t base = ((size_t)b * N_ + s) * C_;
    const float* Qg = IO + base;
    const __half* Kg = g_kv + base;
    const __half* Vg = g_kv + TOT + base;
    float* Ob = IO + base;

    float acc[4][12];
#pragma unroll
    for (int r = 0; r < 4; r++)
#pragma unroll
        for (int c = 0; c < 12; c++) acc[r][c] = 0.f;

    for (int kc = 0; kc < 512; kc += 32) {
#pragma unroll
        for (int it = 0; it < 8; it++) {
            int idx = it * 256 + tid;
            int r = idx >> 5, c = idx & 31;
            Qs[c * 65 + r] = Qg[(size_t)(i0 + r) * TOK_STRIDE + kc + c];
        }
#pragma unroll
        for (int it = 0; it < 12; it++) {
            int idx = it * 256 + tid;
            int j = idx >> 4, c = (idx & 15) << 1;
            int jg = jlo + j;
            float f0 = 0.f, f1 = 0.f;
            if (jg < NB_) {
                __half2 h = *(const __half2*)&Kg[(size_t)jg * TOK_STRIDE + kc + c];
                float2 f = __half22float2(h);
                f0 = f.x; f1 = f.y;
            }
            Ks[c * 193 + j]       = f0;
            Ks[(c + 1) * 193 + j] = f1;
        }
        __syncthreads();
#pragma unroll 8
        for (int k = 0; k < 32; k++) {
            float a[4], bb[12];
#pragma unroll
            for (int r = 0; r < 4; r++) a[r] = Qs[k * 65 + ty + 16 * r];
#pragma unroll
            for (int c = 0; c < 12; c++) bb[c] = Ks[k * 193 + tx + 16 * c];
#pragma unroll
            for (int r = 0; r < 4; r++)
#pragma unroll
                for (int c = 0; c < 12; c++) acc[r][c] += a[r] * bb[c];
        }
        __syncthreads();
    }

#pragma unroll
    for (int r = 0; r < 4; r++) {
        int row = ty + 16 * r;
        int gi = i0 + row;
#pragma unroll
        for (int c = 0; c < 12; c++) {
            int col = tx + 16 * c;
            int jg = jlo + col;
            bool valid = (jg < NB_) && (jg >= gi - 64) && (jg <= gi + 64);
            S[row * 200 + col] = valid ? acc[r][c] * 0.125f : -CUDART_INF_F;
        }
    }
    __syncthreads();

    {
        int warp = tid >> 5, lane = tid & 31;
        for (int row = warp; row < 64; row += 8) {
            float v[6];
            float m = -CUDART_INF_F;
#pragma unroll
            for (int t = 0; t < 6; t++) {
                v[t] = S[row * 200 + lane + 32 * t];
                m = fmaxf(m, v[t]);
            }
#pragma unroll
            for (int o = 16; o > 0; o >>= 1)
                m = fmaxf(m, __shfl_xor_sync(0xffffffffu, m, o));
            float sum = 0.f;
#pragma unroll
            for (int t = 0; t < 6; t++) { v[t] = expf(v[t] - m); sum += v[t]; }
#pragma unroll
            for (int o = 16; o > 0; o >>= 1)
                sum += __shfl_xor_sync(0xffffffffu, sum, o);
            float inv = 1.0f / sum;
#pragma unroll
            for (int t = 0; t < 6; t++) S[row * 200 + lane + 32 * t] = v[t] * inv;
        }
    }
    __syncthreads();

    for (int c0 = 0; c0 < 512; c0 += 64) {
#pragma unroll
        for (int it = 0; it < 24; it++) {
            int idx = it * 256 + tid;
            int j = idx >> 5, c = (idx & 31) << 1;
            int jg = jlo + j;
            float f0 = 0.f, f1 = 0.f;
            if (jg < NB_) {
                __half2 h = *(const __half2*)&Vg[(size_t)jg * TOK_STRIDE + c0 + c];
                float2 f = __half22float2(h);
                f0 = f.x; f1 = f.y;
            }
            Vs[j * 64 + c]     = f0;
            Vs[j * 64 + c + 1] = f1;
        }
        __syncthreads();
        float o[4][4];
#pragma unroll
        for (int r = 0; r < 4; r++)
#pragma unroll
            for (int c = 0; c < 4; c++) o[r][c] = 0.f;
#pragma unroll 4
        for (int j = 0; j < 192; j++) {
            float4 vv = *(const float4*)&Vs[j * 64 + tx * 4];
#pragma unroll
            for (int r = 0; r < 4; r++) {
                float p = S[(ty * 4 + r) * 200 + j];
                o[r][0] += p * vv.x; o[r][1] += p * vv.y;
                o[r][2] += p * vv.z; o[r][3] += p * vv.w;
            }
        }
#pragma unroll
        for (int r = 0; r < 4; r++) {
            int row = ty * 4 + r;
            *(float4*)&Ob[(size_t)(i0 + row) * TOK_STRIDE + c0 + tx * 4] =
                make_float4(o[r][0], o[r][1], o[r][2], o[r][3]);
        }
        __syncthreads();
    }
}

// ---------------------------------------------------------------------------
// Kernel 3: in-place output projection via fp16 tensor cores.
// CTA = 32 exclusive rows x FULL N=512 (in-place safe: all A reads of these
// rows finish before the epilogue writes them; CTAs own disjoint rows).
// BK=16, double-buffered. 8 warps, each 32x64 (same warp tile as qkv_mma).
// ---------------------------------------------------------------------------
__global__ void __launch_bounds__(256) proj_mma(const float* __restrict__ W,
                                                const float* __restrict__ bias,
                                                float* __restrict__ IO)
{
    __shared__ __half As[2][32][24];    // [m][k], pitch 24 halves (48B)
    __shared__ __half Bs[2][16][520];   // [k][n], pitch 520 halves (1040B)

    const int tid  = threadIdx.x;
    const int lane = tid & 31, wid = tid >> 5;
    const int wn = wid << 6;            // warp col offset, 8 warps x 64 = 512
    const int m0 = blockIdx.x << 5;

    const int la_r = tid >> 3, la_k = (tid & 7) << 1;    // A: 1 row, 2 k
    const int lb_k = tid >> 4, lb_n = (tid & 15) << 5;   // B: 1 k, 32 n

    const float* Ap = IO + (size_t)(m0 + la_r) * 512 + la_k;
    const float* Bp = W + (size_t)lb_k * 512 + lb_n;

    float acc[2][8][4];
#pragma unroll
    for (int i = 0; i < 2; i++)
#pragma unroll
        for (int j = 0; j < 8; j++)
#pragma unroll
            for (int c = 0; c < 4; c++) acc[i][j][c] = 0.f;

    float2 fa;
    float4 fb[8];
    fa = *(const float2*)(Ap);
#pragma unroll
    for (int i = 0; i < 8; i++) fb[i] = *(const float4*)(Bp + 4 * i);

    {   // stage tile 0
        __half2 h = __floats2half2_rn(fa.x, fa.y);
        *(uint32_t*)&As[0][la_r][la_k] = *(uint32_t*)&h;
#pragma unroll
        for (int i = 0; i < 4; i++) {
            uint2 u0 = cvt2h2(fb[2 * i]), u1 = cvt2h2(fb[2 * i + 1]);
            *(uint4*)&Bs[0][lb_k][lb_n + 8 * i] = make_uint4(u0.x, u0.y, u1.x, u1.y);
        }
    }
    __syncthreads();

    int buf = 0;
    for (int kt = 0; kt < 512; kt += 16) {
        const bool more = (kt + 16) < 512;
        if (more) {
            fa = *(const float2*)(Ap + kt + 16);
#pragma unroll
            for (int i = 0; i < 8; i++)
                fb[i] = *(const float4*)(Bp + (size_t)(kt + 16) * 512 + 4 * i);
        }
        {
            uint32_t af[2][4];
#pragma unroll
            for (int tm = 0; tm < 2; tm++) {
                uint32_t ad = sptr(&As[buf][tm * 16 + (lane & 15)][(lane >> 4) << 3]);
                LDM_X4(af[tm][0], af[tm][1], af[tm][2], af[tm][3], ad);
            }
            uint32_t bfr[8][2];
#pragma unroll
            for (int g16 = 0; g16 < 4; g16++) {
                uint32_t r0, r1, r2, r3;
                uint32_t bd = sptr(&Bs[buf][(lane & 15)][wn + g16 * 16 + ((lane >> 4) << 3)]);
                LDM_X4T(r0, r1, r2, r3, bd);
                bfr[2 * g16][0] = r0;     bfr[2 * g16][1] = r1;
                bfr[2 * g16 + 1][0] = r2; bfr[2 * g16 + 1][1] = r3;
            }
#pragma unroll
            for (int tm = 0; tm < 2; tm++)
#pragma unroll
                for (int tn = 0; tn < 8; tn++)
                    MMA16816(acc[tm][tn], af[tm], bfr[tn]);
        }
        if (more) {
            int nx = buf ^ 1;
            __half2 h = __floats2half2_rn(fa.x, fa.y);
            *(uint32_t*)&As[nx][la_r][la_k] = *(uint32_t*)&h;
#pragma unroll
            for (int i = 0; i < 4; i++) {
                uint2 u0 = cvt2h2(fb[2 * i]), u1 = cvt2h2(fb[2 * i + 1]);
                *(uint4*)&Bs[nx][lb_k][lb_n + 8 * i] = make_uint4(u0.x, u0.y, u1.x, u1.y);
            }
        }
        __syncthreads();
        buf ^= 1;
    }

    // Epilogue: write back exclusive rows (all reads already done)
    const int g = lane >> 2, q = lane & 3;
#pragma unroll
    for (int tm = 0; tm < 2; tm++) {
        int r0 = m0 + tm * 16 + g;
#pragma unroll
        for (int tn = 0; tn < 8; tn++) {
            int col = wn + tn * 8 + (q << 1);
            float bx = bias[col], by = bias[col + 1];
            *(float2*)&IO[(size_t)r0 * 512 + col] =
                make_float2(acc[tm][tn][0] + bx, acc[tm][tn][1] + by);
            *(float2*)&IO[(size_t)(r0 + 8) * 512 + col] =
                make_float2(acc[tm][tn][2] + bx, acc[tm][tn][3] + by);
        }
    }
}

// ---------------------------------------------------------------------------
extern "C" void kernel_launch(void* const* d_in, const int* in_sizes, int n_in,
                              void* d_out, int out_size)
{
    const float* x     = (const float*)d_in[0];
    const float* Wqkv  = (const float*)d_in[1];
    const float* bqkv  = (const float*)d_in[2];
    const float* Wproj = (const float*)d_in[3];
    const float* bproj = (const float*)d_in[4];
    float* out = (float*)d_out;

    cudaFuncSetAttribute(attn_kernel, cudaFuncAttributeMaxDynamicSharedMemorySize,
                         ATTN_SMEM_BYTES);

    qkv_mma<<<dim3(12, 512), 256>>>(x, Wqkv, bqkv, out);
    attn_kernel<<<dim3(4, 32, 8), 256, ATTN_SMEM_BYTES>>>(out);
    proj_mma<<<2048, 256>>>(Wproj, bproj, out);
}

// round 8
// speedup vs baseline: 2.0565x; 1.3909x over previous
#include <cuda_runtime.h>
#include <cuda_fp16.h>
#include <math_constants.h>
#include <cstdint>

// Problem constants
#define B_   8
#define N_   8192
#define C_   512
#define NB_  256          // number of token-blocks (N/32)
#define TOK_STRIDE 16384  // 32 * C_
#define TOT 33554432      // B_*N_*C_

// Single scratch global: K and V in fp16 (128 MB total). q fp32 lives in d_out.
__device__ __half g_kv[2u * TOT];

// ---------------------------------------------------------------------------
// helpers
// ---------------------------------------------------------------------------
__device__ __forceinline__ uint32_t sptr(const void* p) {
    return (uint32_t)__cvta_generic_to_shared(p);
}
__device__ __forceinline__ uint2 cvt2h2(float4 f) {
    __half2 h0 = __floats2half2_rn(f.x, f.y);
    __half2 h1 = __floats2half2_rn(f.z, f.w);
    uint2 r;
    r.x = *(uint32_t*)&h0;
    r.y = *(uint32_t*)&h1;
    return r;
}

#define LDM_X4(r0, r1, r2, r3, addr)                                         \
    asm volatile("ldmatrix.sync.aligned.m8n8.x4.shared.b16 {%0,%1,%2,%3}, [%4];" \
                 : "=r"(r0), "=r"(r1), "=r"(r2), "=r"(r3) : "r"(addr))
#define LDM_X4T(r0, r1, r2, r3, addr)                                        \
    asm volatile("ldmatrix.sync.aligned.m8n8.x4.trans.shared.b16 {%0,%1,%2,%3}, [%4];" \
                 : "=r"(r0), "=r"(r1), "=r"(r2), "=r"(r3) : "r"(addr))
#define MMA16816(c, a, b)                                                    \
    asm volatile("mma.sync.aligned.m16n8k16.row.col.f32.f16.f16.f32 "        \
                 "{%0,%1,%2,%3}, {%4,%5,%6,%7}, {%8,%9}, {%0,%1,%2,%3};"     \
                 : "+f"((c)[0]), "+f"((c)[1]), "+f"((c)[2]), "+f"((c)[3])    \
                 : "r"((a)[0]), "r"((a)[1]), "r"((a)[2]), "r"((a)[3]),       \
                   "r"((b)[0]), "r"((b)[1]))

// ---------------------------------------------------------------------------
// Kernel 1: QKV GEMM via fp16 tensor cores (unchanged from passing R7 build).
// ---------------------------------------------------------------------------
__global__ void __launch_bounds__(256) qkv_mma(const float* __restrict__ X,
                                               const float* __restrict__ W,
                                               const float* __restrict__ bias,
                                               float* __restrict__ Qf)
{
    __shared__ __half As[2][128][40];
    __shared__ __half Bs[2][32][136];

    const int tid  = threadIdx.x;
    const int lane = tid & 31, wid = tid >> 5;
    const int wm = (wid & 3) << 5;
    const int wn = (wid >> 2) << 6;
    const int m0 = blockIdx.y << 7;
    const int n0 = blockIdx.x << 7;

    const int la_r = tid >> 1, la_k = (tid & 1) << 4;
    const int lb_k = tid >> 3, lb_n = (tid & 7) << 4;

    const float* Ap = X + (size_t)(m0 + la_r) * 512 + la_k;
    const float* Bp = W + (size_t)lb_k * 1536 + n0 + lb_n;

    float acc[2][8][4];
#pragma unroll
    for (int i = 0; i < 2; i++)
#pragma unroll
        for (int j = 0; j < 8; j++)
#pragma unroll
            for (int c = 0; c < 4; c++) acc[i][j][c] = 0.f;

    float4 fa[4], fb[4];
#pragma unroll
    for (int i = 0; i < 4; i++) fa[i] = *(const float4*)(Ap + 4 * i);
#pragma unroll
    for (int i = 0; i < 4; i++) fb[i] = *(const float4*)(Bp + 4 * i);

    {
        uint2 a0 = cvt2h2(fa[0]), a1 = cvt2h2(fa[1]), a2 = cvt2h2(fa[2]), a3 = cvt2h2(fa[3]);
        *(uint4*)&As[0][la_r][la_k]     = make_uint4(a0.x, a0.y, a1.x, a1.y);
        *(uint4*)&As[0][la_r][la_k + 8] = make_uint4(a2.x, a2.y, a3.x, a3.y);
        uint2 b0 = cvt2h2(fb[0]), b1 = cvt2h2(fb[1]), b2 = cvt2h2(fb[2]), b3 = cvt2h2(fb[3]);
        *(uint4*)&Bs[0][lb_k][lb_n]     = make_uint4(b0.x, b0.y, b1.x, b1.y);
        *(uint4*)&Bs[0][lb_k][lb_n + 8] = make_uint4(b2.x, b2.y, b3.x, b3.y);
    }
    __syncthreads();

    int buf = 0;
    for (int kt = 0; kt < 512; kt += 32) {
        const bool more = (kt + 32) < 512;
        if (more) {
#pragma unroll
            for (int i = 0; i < 4; i++) fa[i] = *(const float4*)(Ap + kt + 32 + 4 * i);
#pragma unroll
            for (int i = 0; i < 4; i++) fb[i] = *(const float4*)(Bp + (size_t)(kt + 32) * 1536 + 4 * i);
        }
#pragma unroll
        for (int kk = 0; kk < 2; kk++) {
            uint32_t af[2][4];
#pragma unroll
            for (int tm = 0; tm < 2; tm++) {
                uint32_t ad = sptr(&As[buf][wm + tm * 16 + (lane & 15)][kk * 16 + ((lane >> 4) << 3)]);
                LDM_X4(af[tm][0], af[tm][1], af[tm][2], af[tm][3], ad);
            }
            uint32_t bfr[8][2];
#pragma unroll
            for (int g16 = 0; g16 < 4; g16++) {
                uint32_t r0, r1, r2, r3;
                uint32_t bd = sptr(&Bs[buf][kk * 16 + (lane & 15)][wn + g16 * 16 + ((lane >> 4) << 3)]);
                LDM_X4T(r0, r1, r2, r3, bd);
                bfr[2 * g16][0] = r0;     bfr[2 * g16][1] = r1;
                bfr[2 * g16 + 1][0] = r2; bfr[2 * g16 + 1][1] = r3;
            }
#pragma unroll
            for (int tm = 0; tm < 2; tm++)
#pragma unroll
                for (int tn = 0; tn < 8; tn++)
                    MMA16816(acc[tm][tn], af[tm], bfr[tn]);
        }
        if (more) {
            int nx = buf ^ 1;
            uint2 a0 = cvt2h2(fa[0]), a1 = cvt2h2(fa[1]), a2 = cvt2h2(fa[2]), a3 = cvt2h2(fa[3]);
            *(uint4*)&As[nx][la_r][la_k]     = make_uint4(a0.x, a0.y, a1.x, a1.y);
            *(uint4*)&As[nx][la_r][la_k + 8] = make_uint4(a2.x, a2.y, a3.x, a3.y);
            uint2 b0 = cvt2h2(fb[0]), b1 = cvt2h2(fb[1]), b2 = cvt2h2(fb[2]), b3 = cvt2h2(fb[3]);
            *(uint4*)&Bs[nx][lb_k][lb_n]     = make_uint4(b0.x, b0.y, b1.x, b1.y);
            *(uint4*)&Bs[nx][lb_k][lb_n + 8] = make_uint4(b2.x, b2.y, b3.x, b3.y);
        }
        __syncthreads();
        buf ^= 1;
    }

    const int g = lane >> 2, q = lane & 3;
#pragma unroll
    for (int tm = 0; tm < 2; tm++) {
        int r0 = m0 + wm + tm * 16 + g;
#pragma unroll
        for (int tn = 0; tn < 8; tn++) {
            int col = n0 + wn + tn * 8 + (q << 1);
            float bx = bias[col], by = bias[col + 1];
            int part = (col % 192) >> 6;
            int c = ((col / 192) << 6) + (col & 63);
            float vx0 = acc[tm][tn][0] + bx, vy0 = acc[tm][tn][1] + by;
            float vx1 = acc[tm][tn][2] + bx, vy1 = acc[tm][tn][3] + by;
            if (part == 0) {
                *(float2*)&Qf[(size_t)r0 * 512 + c]       = make_float2(vx0, vy0);
                *(float2*)&Qf[(size_t)(r0 + 8) * 512 + c] = make_float2(vx1, vy1);
            } else {
                __half* dst = g_kv + (part == 1 ? 0u : (unsigned)TOT);
                *(__half2*)&dst[(size_t)r0 * 512 + c]       = __floats2half2_rn(vx0, vy0);
                *(__half2*)&dst[(size_t)(r0 + 8) * 512 + c] = __floats2half2_rn(vx1, vy1);
            }
        }
    }
}

// ---------------------------------------------------------------------------
// Kernel 2: banded block attention via tensor cores.
// CTA = (b, s, i-tile of 64 blocks); j-window = 192 at jlo.
// Phase 1: S = Q·K^T, warp tile 32x48, k-chunks of 64. fp32 softmax -> Ps fp16.
// Phase 2: O = P·V over 128-wide c-chunks, warp tile 32x32.
// Smem: S[64][200] f32 | Ps[64][200] f16 | union(Qh[64][72]+Kh[192][72], Vh[192][136]) f16
// ---------------------------------------------------------------------------
#define ATTN_SMEM_BYTES 129024

__global__ void __launch_bounds__(256) attn_kernel(float* __restrict__ IO)
{
    extern __shared__ float sm[];
    float*  S  = sm;                          // [64][200] fp32
    __half* Ps = (__half*)(sm + 12800);       // [64][200] fp16
    __half* Qh = (__half*)(sm + 19200);       // [64][72]   (phase 1)
    __half* Kh = Qh + 64 * 72;                // [192][72]  (phase 1)
    __half* Vh = Qh;                          // [192][136] (phase 2 alias)

    const int tid  = threadIdx.x;
    const int lane = tid & 31, wid = tid >> 5;
    const int g = lane >> 2, q = lane & 3;
    const int i0 = blockIdx.x * 64;
    const int s  = blockIdx.y;
    const int b  = blockIdx.z;
    const int jlo = (i0 - 64 > 0) ? (i0 - 64) : 0;

    const size_t base = ((size_t)b * N_ + s) * C_;
    const float* Qg = IO + base;
    const __half* Kg = g_kv + base;
    const __half* Vg = g_kv + TOT + base;
    float* Ob = IO + base;

    const int wm1 = (wid & 1) << 5;       // phase1/2 m offset: 0/32
    const int wn1 = (wid >> 1) * 48;      // phase1 n offset: 0/48/96/144
    const int wc  = (wid >> 1) << 5;      // phase2 c offset: 0/32/64/96

    // ---- Phase 1: S = Q K^T, k-chunks of 64 ----
    float acc1[2][6][4];
#pragma unroll
    for (int a = 0; a < 2; a++)
#pragma unroll
        for (int bb = 0; bb < 6; bb++)
#pragma unroll
            for (int c = 0; c < 4; c++) acc1[a][bb][c] = 0.f;

    for (int kc = 0; kc < 512; kc += 64) {
        // Q fill: 64 rows x 64 k, fp32->fp16 (1024 float4s, 4 iters)
#pragma unroll
        for (int it = 0; it < 4; it++) {
            int idx = it * 256 + tid;
            int r = idx >> 4, u = (idx & 15) << 2;
            float4 f = *(const float4*)&Qg[(size_t)(i0 + r) * TOK_STRIDE + kc + u];
            uint2 h = cvt2h2(f);
            *(uint2*)&Qh[r * 72 + u] = h;
        }
        // K fill: 192 rows x 64 k, fp16 uint4 copies (1536 ops, 6 iters)
#pragma unroll
        for (int it = 0; it < 6; it++) {
            int idx = it * 256 + tid;
            int j = idx >> 3, u = (idx & 7) << 3;
            int jg = jlo + j;
            uint4 v = make_uint4(0, 0, 0, 0);
            if (jg < NB_)
                v = *(const uint4*)&Kg[(size_t)jg * TOK_STRIDE + kc + u];
            *(uint4*)&Kh[j * 72 + u] = v;
        }
        __syncthreads();
#pragma unroll
        for (int kk = 0; kk < 4; kk++) {
            const int kb = kk << 4;
            uint32_t af[2][4];
#pragma unroll
            for (int tm = 0; tm < 2; tm++) {
                uint32_t ad = sptr(&Qh[(wm1 + tm * 16 + (lane & 15)) * 72 + kb + ((lane >> 4) << 3)]);
                LDM_X4(af[tm][0], af[tm][1], af[tm][2], af[tm][3], ad);
            }
            uint32_t bf[6][2];
#pragma unroll
            for (int t = 0; t < 3; t++) {
                uint32_t r0, r1, r2, r3;
                uint32_t ad = sptr(&Kh[(wn1 + t * 16 + (lane & 15)) * 72 + kb + ((lane >> 4) << 3)]);
                LDM_X4(r0, r1, r2, r3, ad);
                bf[2 * t][0] = r0;     bf[2 * t][1] = r2;   // n8 low : k0-7, k8-15
                bf[2 * t + 1][0] = r1; bf[2 * t + 1][1] = r3; // n8 high
            }
#pragma unroll
            for (int tm = 0; tm < 2; tm++)
#pragma unroll
                for (int tn = 0; tn < 6; tn++)
                    MMA16816(acc1[tm][tn], af[tm], bf[tn]);
        }
        __syncthreads();
    }

    // ---- masked scores -> S (fp32) ----
#pragma unroll
    for (int tm = 0; tm < 2; tm++) {
        int r0 = wm1 + tm * 16 + g;
        int gi0 = i0 + r0, gi1 = gi0 + 8;
#pragma unroll
        for (int tn = 0; tn < 6; tn++) {
            int col = wn1 + tn * 8 + (q << 1);
            int j0 = jlo + col, j1 = j0 + 1;
            bool v00 = (j0 < NB_) && (j0 >= gi0 - 64) && (j0 <= gi0 + 64);
            bool v01 = (j1 < NB_) && (j1 >= gi0 - 64) && (j1 <= gi0 + 64);
            bool v10 = (j0 < NB_) && (j0 >= gi1 - 64) && (j0 <= gi1 + 64);
            bool v11 = (j1 < NB_) && (j1 >= gi1 - 64) && (j1 <= gi1 + 64);
            S[r0 * 200 + col]           = v00 ? acc1[tm][tn][0] * 0.125f : -CUDART_INF_F;
            S[r0 * 200 + col + 1]       = v01 ? acc1[tm][tn][1] * 0.125f : -CUDART_INF_F;
            S[(r0 + 8) * 200 + col]     = v10 ? acc1[tm][tn][2] * 0.125f : -CUDART_INF_F;
            S[(r0 + 8) * 200 + col + 1] = v11 ? acc1[tm][tn][3] * 0.125f : -CUDART_INF_F;
        }
    }
    __syncthreads();

    // ---- softmax (fp32, exact) -> Ps fp16 ----
    for (int row = wid; row < 64; row += 8) {
        float v[6];
        float m = -CUDART_INF_F;
#pragma unroll
        for (int t = 0; t < 6; t++) {
            v[t] = S[row * 200 + lane + 32 * t];
            m = fmaxf(m, v[t]);
        }
#pragma unroll
        for (int o = 16; o > 0; o >>= 1)
            m = fmaxf(m, __shfl_xor_sync(0xffffffffu, m, o));
        float sum = 0.f;
#pragma unroll
        for (int t = 0; t < 6; t++) { v[t] = expf(v[t] - m); sum += v[t]; }
#pragma unroll
        for (int o = 16; o > 0; o >>= 1)
            sum += __shfl_xor_sync(0xffffffffu, sum, o);
        float inv = 1.0f / sum;
#pragma unroll
        for (int t = 0; t < 6; t++)
            Ps[row * 200 + lane + 32 * t] = __float2half(v[t] * inv);
    }
    __syncthreads();

    // ---- Phase 2: O = P V, 128-wide c chunks ----
    for (int c0 = 0; c0 < 512; c0 += 128) {
        // V fill: 192 rows x 128 c (3072 uint4s, 12 iters)
#pragma unroll
        for (int it = 0; it < 12; it++) {
            int idx = it * 256 + tid;
            int j = idx >> 4, u = (idx & 15) << 3;
            int jg = jlo + j;
            uint4 v = make_uint4(0, 0, 0, 0);
            if (jg < NB_)
                v = *(const uint4*)&Vg[(size_t)jg * TOK_STRIDE + c0 + u];
            *(uint4*)&Vh[j * 136 + u] = v;
        }
        __syncthreads();

        float acc2[2][4][4];
#pragma unroll
        for (int a = 0; a < 2; a++)
#pragma unroll
            for (int bb = 0; bb < 4; bb++)
#pragma unroll
                for (int c = 0; c < 4; c++) acc2[a][bb][c] = 0.f;

#pragma unroll
        for (int kk = 0; kk < 12; kk++) {
            const int kb = kk << 4;
            uint32_t af[2][4];
#pragma unroll
            for (int tm = 0; tm < 2; tm++) {
                uint32_t ad = sptr(&Ps[(wm1 + tm * 16 + (lane & 15)) * 200 + kb + ((lane >> 4) << 3)]);
                LDM_X4(af[tm][0], af[tm][1], af[tm][2], af[tm][3], ad);
            }
            uint32_t bf[4][2];
#pragma unroll
            for (int t = 0; t < 2; t++) {
                uint32_t r0, r1, r2, r3;
                uint32_t ad = sptr(&Vh[(kb + (lane & 15)) * 136 + wc + t * 16 + ((lane >> 4) << 3)]);
                LDM_X4T(r0, r1, r2, r3, ad);
                bf[2 * t][0] = r0;     bf[2 * t][1] = r1;
                bf[2 * t + 1][0] = r2; bf[2 * t + 1][1] = r3;
            }
#pragma unroll
            for (int tm = 0; tm < 2; tm++)
#pragma unroll
                for (int tn = 0; tn < 4; tn++)
                    MMA16816(acc2[tm][tn], af[tm], bf[tn]);
        }

        // epilogue for this c chunk
#pragma unroll
        for (int tm = 0; tm < 2; tm++) {
            int row = i0 + wm1 + tm * 16 + g;
#pragma unroll
            for (int tn = 0; tn < 4; tn++) {
                int col = c0 + wc + tn * 8 + (q << 1);
                *(float2*)&Ob[(size_t)row * TOK_STRIDE + col] =
                    make_float2(acc2[tm][tn][0], acc2[tm][tn][1]);
                *(float2*)&Ob[(size_t)(row + 8) * TOK_STRIDE + col] =
                    make_float2(acc2[tm][tn][2], acc2[tm][tn][3]);
            }
        }
        __syncthreads();
    }
}

// ---------------------------------------------------------------------------
// Kernel 3: in-place output projection via fp16 tensor cores (unchanged R7).
// ---------------------------------------------------------------------------
__global__ void __launch_bounds__(256) proj_mma(const float* __restrict__ W,
                                                const float* __restrict__ bias,
                                                float* __restrict__ IO)
{
    __shared__ __half As[2][32][24];
    __shared__ __half Bs[2][16][520];

    const int tid  = threadIdx.x;
    const int lane = tid & 31, wid = tid >> 5;
    const int wn = wid << 6;
    const int m0 = blockIdx.x << 5;

    const int la_r = tid >> 3, la_k = (tid & 7) << 1;
    const int lb_k = tid >> 4, lb_n = (tid & 15) << 5;

    const float* Ap = IO + (size_t)(m0 + la_r) * 512 + la_k;
    const float* Bp = W + (size_t)lb_k * 512 + lb_n;

    float acc[2][8][4];
#pragma unroll
    for (int i = 0; i < 2; i++)
#pragma unroll
        for (int j = 0; j < 8; j++)
#pragma unroll
            for (int c = 0; c < 4; c++) acc[i][j][c] = 0.f;

    float2 fa;
    float4 fb[8];
    fa = *(const float2*)(Ap);
#pragma unroll
    for (int i = 0; i < 8; i++) fb[i] = *(const float4*)(Bp + 4 * i);

    {
        __half2 h = __floats2half2_rn(fa.x, fa.y);
        *(uint32_t*)&As[0][la_r][la_k] = *(uint32_t*)&h;
#pragma unroll
        for (int i = 0; i < 4; i++) {
            uint2 u0 = cvt2h2(fb[2 * i]), u1 = cvt2h2(fb[2 * i + 1]);
            *(uint4*)&Bs[0][lb_k][lb_n + 8 * i] = make_uint4(u0.x, u0.y, u1.x, u1.y);
        }
    }
    __syncthreads();

    int buf = 0;
    for (int kt = 0; kt < 512; kt += 16) {
        const bool more = (kt + 16) < 512;
        if (more) {
            fa = *(const float2*)(Ap + kt + 16);
#pragma unroll
            for (int i = 0; i < 8; i++)
                fb[i] = *(const float4*)(Bp + (size_t)(kt + 16) * 512 + 4 * i);
        }
        {
            uint32_t af[2][4];
#pragma unroll
            for (int tm = 0; tm < 2; tm++) {
                uint32_t ad = sptr(&As[buf][tm * 16 + (lane & 15)][(lane >> 4) << 3]);
                LDM_X4(af[tm][0], af[tm][1], af[tm][2], af[tm][3], ad);
            }
            uint32_t bfr[8][2];
#pragma unroll
            for (int g16 = 0; g16 < 4; g16++) {
                uint32_t r0, r1, r2, r3;
                uint32_t bd = sptr(&Bs[buf][(lane & 15)][wn + g16 * 16 + ((lane >> 4) << 3)]);
                LDM_X4T(r0, r1, r2, r3, bd);
                bfr[2 * g16][0] = r0;     bfr[2 * g16][1] = r1;
                bfr[2 * g16 + 1][0] = r2; bfr[2 * g16 + 1][1] = r3;
            }
#pragma unroll
            for (int tm = 0; tm < 2; tm++)
#pragma unroll
                for (int tn = 0; tn < 8; tn++)
                    MMA16816(acc[tm][tn], af[tm], bfr[tn]);
        }
        if (more) {
            int nx = buf ^ 1;
            __half2 h = __floats2half2_rn(fa.x, fa.y);
            *(uint32_t*)&As[nx][la_r][la_k] = *(uint32_t*)&h;
#pragma unroll
            for (int i = 0; i < 4; i++) {
                uint2 u0 = cvt2h2(fb[2 * i]), u1 = cvt2h2(fb[2 * i + 1]);
                *(uint4*)&Bs[nx][lb_k][lb_n + 8 * i] = make_uint4(u0.x, u0.y, u1.x, u1.y);
            }
        }
        __syncthreads();
        buf ^= 1;
    }

    const int g = lane >> 2, q = lane & 3;
#pragma unroll
    for (int tm = 0; tm < 2; tm++) {
        int r0 = m0 + tm * 16 + g;
#pragma unroll
        for (int tn = 0; tn < 8; tn++) {
            int col = wn + tn * 8 + (q << 1);
            float bx = bias[col], by = bias[col + 1];
            *(float2*)&IO[(size_t)r0 * 512 + col] =
                make_float2(acc[tm][tn][0] + bx, acc[tm][tn][1] + by);
            *(float2*)&IO[(size_t)(r0 + 8) * 512 + col] =
                make_float2(acc[tm][tn][2] + bx, acc[tm][tn][3] + by);
        }
    }
}

// ---------------------------------------------------------------------------
extern "C" void kernel_launch(void* const* d_in, const int* in_sizes, int n_in,
                              void* d_out, int out_size)
{
    const float* x     = (const float*)d_in[0];
    const float* Wqkv  = (const float*)d_in[1];
    const float* bqkv  = (const float*)d_in[2];
    const float* Wproj = (const float*)d_in[3];
    const float* bproj = (const float*)d_in[4];
    float* out = (float*)d_out;

    cudaFuncSetAttribute(attn_kernel, cudaFuncAttributeMaxDynamicSharedMemorySize,
                         ATTN_SMEM_BYTES);

    qkv_mma<<<dim3(12, 512), 256>>>(x, Wqkv, bqkv, out);
    attn_kernel<<<dim3(4, 32, 8), 256, ATTN_SMEM_BYTES>>>(out);
    proj_mma<<<2048, 256>>>(Wproj, bproj, out);
}